// round 14
// baseline (speedup 1.0000x reference)
#include <cuda_runtime.h>
#include <cuda_bf16.h>
#include <cstdint>

#define HID   512
#define BATCH 256
#define TLEN  1024
#define GRID  128
#define NTHR  256

// smem byte offsets
#define SM_A      0                      // 96 chunks x 2 mh x 1024B = 196608
#define GSTRIDE   132
#define SM_G0     196608                 // 32 x 132 fp32 = 16896
#define SM_G1     213504                 // 16896
#define SM_WIH1   230400                 // 32 fp32
#define SM_B1     230528
#define SM_B2     230656
#define SM_TOTAL  230784

// B-fragment image: [kc(32)][nb(2)][tile(16)][lane(32)][16B]
// 16B = {b0hi,b1hi,b0lo,b1lo}; 32 chunks x 16384B = 524288B
__device__ __align__(16) unsigned char g_h1img[2][524288];
__device__ __align__(16) unsigned char g_h2img[2][524288];
__device__ float g_h2f32[2][BATCH * HID];   // [b][u] for the output head
__device__ float g_xT[TLEN * BATCH];        // x transposed [t][b]
__device__ unsigned long long g_epoch;
__device__ unsigned g_cnt;

#define MMA_BF16(D, A0, A1, A2, A3, B0, B1)                                   \
    asm volatile(                                                             \
        "mma.sync.aligned.m16n8k16.row.col.f32.bf16.bf16.f32 "                \
        "{%0,%1,%2,%3}, {%4,%5,%6,%7}, {%8,%9}, {%0,%1,%2,%3};"               \
        : "+f"((D)[0]), "+f"((D)[1]), "+f"((D)[2]), "+f"((D)[3])              \
        : "r"(A0), "r"(A1), "r"(A2), "r"(A3), "r"(B0), "r"(B1))

__device__ __forceinline__ float sigm_f(float v) {
    return __fdividef(1.f, 1.f + __expf(-v));
}
__device__ __forceinline__ float tanh_f(float v) {
    float e = __expf(2.f * v);
    return 1.f - __fdividef(2.f, e + 1.f);
}

__device__ __forceinline__ void grid_bar(unsigned long long& target, int tid) {
    __threadfence();
    __syncthreads();
    if (tid == 0) {
        target += 1;
        unsigned prev = atomicAdd(&g_cnt, 1u);
        if (prev == GRID - 1) {
            g_cnt = 0;
            __threadfence();
            atomicAdd(&g_epoch, 1ull);
        } else {
            while (*((volatile unsigned long long*)&g_epoch) < target) { }
        }
        __threadfence();
    }
    __syncthreads();
}

// ---- n64 warp-tile GEMM pieces ----
__device__ __forceinline__ void loadB8(uint4 B[8], const char* bimg, int c) {
#pragma unroll
    for (int t = 0; t < 8; t++)
        B[t] = *(const uint4*)(bimg + c * 16384 + t * 512);
}
__device__ __forceinline__ void loadA4(uint4 A[4], const char* ab, int c) {
    A[0] = *(const uint4*)(ab + c * 2048);          // mh0 hi
    A[1] = *(const uint4*)(ab + c * 2048 + 512);    // mh0 lo
    A[2] = *(const uint4*)(ab + c * 2048 + 1024);   // mh1 hi
    A[3] = *(const uint4*)(ab + c * 2048 + 1536);   // mh1 lo
}
// one chunk: 2 mh x 8 n8-tiles x 3 MMAs = 48 MMAs
__device__ __forceinline__ void comp8(float d[16][4], const uint4 A[4],
                                      const uint4 B[8]) {
#pragma unroll
    for (int t = 0; t < 8; t++) {
        uint4 Bv = B[t];
        MMA_BF16(d[t],     A[0].x, A[0].y, A[0].z, A[0].w, Bv.x, Bv.y);  // hi*hi
        MMA_BF16(d[t],     A[0].x, A[0].y, A[0].z, A[0].w, Bv.z, Bv.w);  // hi*lo
        MMA_BF16(d[t],     A[1].x, A[1].y, A[1].z, A[1].w, Bv.x, Bv.y);  // lo*hi
        MMA_BF16(d[8 + t], A[2].x, A[2].y, A[2].z, A[2].w, Bv.x, Bv.y);
        MMA_BF16(d[8 + t], A[2].x, A[2].y, A[2].z, A[2].w, Bv.z, Bv.w);
        MMA_BF16(d[8 + t], A[3].x, A[3].y, A[3].z, A[3].w, Bv.x, Bv.y);
    }
}
// 8 chunks, A+B ping-pong double buffered
__device__ __forceinline__ void gemm8(float d[16][4], const char* ab,
                                      const char* bimg) {
    uint4 Bb[2][8], Ab[2][4];
    loadB8(Bb[0], bimg, 0);
    loadA4(Ab[0], ab, 0);
#pragma unroll
    for (int c = 0; c < 8; c++) {
        int cur = c & 1;
        if (c < 7) { loadB8(Bb[cur ^ 1], bimg, c + 1); loadA4(Ab[cur ^ 1], ab, c + 1); }
        comp8(d, Ab[cur], Bb[cur]);
    }
}

// fragment -> gates buffer (store or accumulate)
__device__ __forceinline__ void frag_out(float* gbuf, const float d[16][4],
                                         int ns, int lane, bool add) {
    int cb = ns * 64 + 2 * (lane & 3);
    int rr = lane >> 2;
#pragma unroll
    for (int mhp = 0; mhp < 2; mhp++)
#pragma unroll
        for (int tl = 0; tl < 8; tl++) {
            const float* dd = d[mhp * 8 + tl];
            float* p0 = &gbuf[(mhp * 16 + rr) * GSTRIDE + cb + tl * 8];
            float* p1 = &gbuf[(mhp * 16 + rr + 8) * GSTRIDE + cb + tl * 8];
            if (add) {
                float2 v0 = *(float2*)p0; v0.x += dd[0]; v0.y += dd[1]; *(float2*)p0 = v0;
                float2 v1 = *(float2*)p1; v1.x += dd[2]; v1.y += dd[3]; *(float2*)p1 = v1;
            } else {
                *(float2*)p0 = make_float2(dd[0], dd[1]);
                *(float2*)p1 = make_float2(dd[2], dd[3]);
            }
        }
}

__global__ __launch_bounds__(NTHR, 1)
void lstm_mma(const float* __restrict__ x, const float* __restrict__ W_ih1,
              const float* __restrict__ W_hh1, const float* __restrict__ b1,
              const float* __restrict__ W_ih2, const float* __restrict__ W_hh2,
              const float* __restrict__ b2, const float* __restrict__ W_lin,
              const float* __restrict__ b_lin, float* __restrict__ out)
{
    extern __shared__ char smch[];
    const int tid = threadIdx.x, wid = tid >> 5, lane = tid & 31;
    const int bk = blockIdx.x;
    const int rt = bk >> 1;          // row-tile 0..63 (units rt*8 .. rt*8+7)
    const int nb = bk & 1;           // batch half
    const int kq = wid >> 1;         // K-quarter 0..3
    const int ns = wid & 1;          // n64 slice 0/1

    unsigned long long bar_target = 0;
    if (tid == 0) bar_target = *((volatile unsigned long long*)&g_epoch);

    float* g0   = (float*)(smch + SM_G0);
    float* g1   = (float*)(smch + SM_G1);
    float* wih1 = (float*)(smch + SM_WIH1);
    float* b1s  = (float*)(smch + SM_B1);
    float* b2s  = (float*)(smch + SM_B2);

    if (tid < 32) {
        int grow = (tid & 3) * HID + rt * 8 + (tid >> 2);
        wih1[tid] = W_ih1[grow];
        b1s[tid]  = b1[grow];
        b2s[tid]  = b2[grow];
    }
    const float blin = b_lin[0];

    // ---- A pack: 96 chunks x 2 mh x 32 lane x 4 regs, hi/lo bf16 ----
    for (int idx = tid; idx < 96 * 2 * 32 * 4; idx += NTHR) {
        int j = idx & 3, l = (idx >> 2) & 31, mhp = (idx >> 7) & 1, c = idx >> 8;
        int m16row = (j & 1) * 8 + (l >> 2);
        int r = mhp * 16 + m16row;
        int grow = (r & 3) * HID + rt * 8 + (r >> 2);
        int kk0 = ((j >> 1) & 1) * 8 + 2 * (l & 3);
        float w0, w1;
        if (c < 32) {
            int kg = c * 16 + kk0;
            w0 = W_hh1[grow * HID + kg]; w1 = W_hh1[grow * HID + kg + 1];
        } else {
            int kl = (c - 32) * 16 + kk0;
            if (kl < HID) { w0 = W_ih2[grow * HID + kl]; w1 = W_ih2[grow * HID + kl + 1]; }
            else { w0 = W_hh2[grow * HID + kl - HID]; w1 = W_hh2[grow * HID + kl - HID + 1]; }
        }
        __nv_bfloat16 h0 = __float2bfloat16(w0), h1v = __float2bfloat16(w1);
        __nv_bfloat16 l0 = __float2bfloat16(w0 - __bfloat162float(h0));
        __nv_bfloat16 l1 = __float2bfloat16(w1 - __bfloat162float(h1v));
        uint32_t hp = ((uint32_t)*(uint16_t*)&h1v << 16) | *(uint16_t*)&h0;
        uint32_t lp = ((uint32_t)*(uint16_t*)&l1  << 16) | *(uint16_t*)&l0;
        char* base = smch + SM_A + c * 2048 + mhp * 1024 + l * 16 + j * 4;
        *(uint32_t*)base = hp;
        *(uint32_t*)(base + 512) = lp;
    }

    // ---- global prologue ----
    {
        const int gt = bk * NTHR + tid, gs = GRID * NTHR;
        unsigned long long* z1 = (unsigned long long*)g_h1img[0];
        unsigned long long* z2 = (unsigned long long*)g_h2img[0];
        for (int i = gt; i < 524288 / 8; i += gs) { z1[i] = 0ull; z2[i] = 0ull; }
        for (int i = gt; i < TLEN * BATCH; i += gs)
            g_xT[(i & (TLEN - 1)) * BATCH + (i >> 10)] = x[i];
    }
    grid_bar(bar_target, tid);

    // activation partition: unit u = tid>>5 (0..7), batches bq..bq+3
    float c1r[4] = {0.f, 0.f, 0.f, 0.f};
    float c2r[4] = {0.f, 0.f, 0.f, 0.f};
    const int u = tid >> 5, bq = (tid & 31) * 4;
    const int ug = rt * 8 + u;
    const int kcw = ug >> 4, kk = ug & 15, kk7 = kk & 7;
    const size_t woffW = (size_t)kcw * 16384 + ((kk < 8) ? 0 : 4) + (kk & 1) * 2;

    // per-warp B base: disjoint n64 slice + K-quarter offset
    const size_t woff = (size_t)nb * 8192 + (size_t)ns * 4096 + lane * 16
                      + (size_t)kq * 8 * 16384;
    const char* ab1  = smch + SM_A + (kq * 8) * 2048 + lane * 16;        // L1 W_hh1
    const char* ab2a = smch + SM_A + (32 + kq * 8) * 2048 + lane * 16;   // L2 W_ih2
    const char* ab2b = smch + SM_A + (64 + kq * 8) * 2048 + lane * 16;   // L2 W_hh2
    float* gb = (kq < 2) ? g0 : g1;
    const bool second = (kq & 1);    // kq 1,3 accumulate after kq 0,2 store

    float d[16][4];

    for (int t = 0; t < TLEN; t++) {
        const int pr = t & 1, pw = pr ^ 1;

        // ================= phase A: layer-1 gates =================
#pragma unroll
        for (int i = 0; i < 64; i++) d[i >> 2][i & 3] = 0.f;
        gemm8(d, ab1, (const char*)g_h1img[pr] + woff);

        if (!second) frag_out(gb, d, ns, lane, false);
        __syncthreads();
        if (second)  frag_out(gb, d, ns, lane, true);
        __syncthreads();
        {   // layer-1 activation
            unsigned char* img = g_h1img[pw];
            float4 xv = *(const float4*)&g_xT[t * BATCH + nb * 128 + bq];
            float gv[4][4];
#pragma unroll
            for (int gi_ = 0; gi_ < 4; gi_++) {
                float4 v0 = *(const float4*)&g0[(4 * u + gi_) * GSTRIDE + bq];
                float4 v1 = *(const float4*)&g1[(4 * u + gi_) * GSTRIDE + bq];
                float bb = b1s[4 * u + gi_];
                float ww = wih1[4 * u + gi_];
                gv[gi_][0] = v0.x + v1.x + bb + ww * xv.x;
                gv[gi_][1] = v0.y + v1.y + bb + ww * xv.y;
                gv[gi_][2] = v0.z + v1.z + bb + ww * xv.z;
                gv[gi_][3] = v0.w + v1.w + bb + ww * xv.w;
            }
#pragma unroll
            for (int e = 0; e < 4; e++) {
                float i_ = sigm_f(gv[0][e]);
                float f_ = sigm_f(gv[1][e]);
                float o_ = sigm_f(gv[3][e]);
                float c = f_ * c1r[e] + i_ * tanh_f(gv[2][e]);
                c1r[e] = c;
                float hv = o_ * tanh_f(c);
                __nv_bfloat16 hh = __float2bfloat16(hv);
                __nv_bfloat16 hl = __float2bfloat16(hv - __bfloat162float(hh));
                int bl = bq + e;
                int c32 = bl & 31, tile = c32 >> 3, col8 = c32 & 7;
                int ln = col8 * 4 + (kk7 >> 1);
                size_t off = woffW + (size_t)(nb * 4 + (bl >> 5)) * 2048 + tile * 512 + ln * 16;
                *(__nv_bfloat16*)(img + off) = hh;
                *(__nv_bfloat16*)(img + off + 8) = hl;
            }
        }

        grid_bar(bar_target, tid);   // the ONLY grid barrier per step

        // ---- output head y(t-1): h2f32[pr] written at B(t-1) ----
        if (t > 0 && wid < 2) {
            int b = 2 * bk + wid;
            const float* hb = g_h2f32[pr] + b * HID;
            float s = 0.f;
#pragma unroll
            for (int i = 0; i < 16; i++)
                s += __ldg(&W_lin[lane + 32 * i]) * hb[lane + 32 * i];
#pragma unroll
            for (int o = 16; o > 0; o >>= 1) s += __shfl_xor_sync(~0u, s, o);
            if (lane == 0) out[b * TLEN + t - 1] = s + blin;
        }

        // ================= phase B: layer-2 gates =================
#pragma unroll
        for (int i = 0; i < 64; i++) d[i >> 2][i & 3] = 0.f;
        gemm8(d, ab2a, (const char*)g_h1img[pw] + woff);
        gemm8(d, ab2b, (const char*)g_h2img[pr] + woff);

        if (!second) frag_out(gb, d, ns, lane, false);
        __syncthreads();
        if (second)  frag_out(gb, d, ns, lane, true);
        __syncthreads();
        {   // layer-2 activation
            unsigned char* img = g_h2img[pw];
            float* h2o = g_h2f32[pw];
            float gv[4][4];
#pragma unroll
            for (int gi_ = 0; gi_ < 4; gi_++) {
                float4 v0 = *(const float4*)&g0[(4 * u + gi_) * GSTRIDE + bq];
                float4 v1 = *(const float4*)&g1[(4 * u + gi_) * GSTRIDE + bq];
                float bb = b2s[4 * u + gi_];
                gv[gi_][0] = v0.x + v1.x + bb;
                gv[gi_][1] = v0.y + v1.y + bb;
                gv[gi_][2] = v0.z + v1.z + bb;
                gv[gi_][3] = v0.w + v1.w + bb;
            }
#pragma unroll
            for (int e = 0; e < 4; e++) {
                float i_ = sigm_f(gv[0][e]);
                float f_ = sigm_f(gv[1][e]);
                float o_ = sigm_f(gv[3][e]);
                float c = f_ * c2r[e] + i_ * tanh_f(gv[2][e]);
                c2r[e] = c;
                float hv = o_ * tanh_f(c);
                __nv_bfloat16 hh = __float2bfloat16(hv);
                __nv_bfloat16 hl = __float2bfloat16(hv - __bfloat162float(hh));
                int bl = bq + e, bg = nb * 128 + bl;
                int c32 = bl & 31, tile = c32 >> 3, col8 = c32 & 7;
                int ln = col8 * 4 + (kk7 >> 1);
                size_t off = woffW + (size_t)(nb * 4 + (bl >> 5)) * 2048 + tile * 512 + ln * 16;
                *(__nv_bfloat16*)(img + off) = hh;
                *(__nv_bfloat16*)(img + off + 8) = hl;
                h2o[bg * HID + ug] = hv;
            }
        }
        __syncthreads();   // protect gates smem vs next step's stores
    }

    // ---- final output y(T-1) ----
    grid_bar(bar_target, tid);
    if (wid < 2) {
        int b = 2 * bk + wid;
        const float* hb = g_h2f32[0] + b * HID;
        float s = 0.f;
#pragma unroll
        for (int i = 0; i < 16; i++)
            s += __ldg(&W_lin[lane + 32 * i]) * hb[lane + 32 * i];
#pragma unroll
        for (int o = 16; o > 0; o >>= 1) s += __shfl_xor_sync(~0u, s, o);
        if (lane == 0) out[b * TLEN + TLEN - 1] = s + blin;
    }
}

extern "C" void kernel_launch(void* const* d_in, const int* in_sizes, int n_in,
                              void* d_out, int out_size)
{
    (void)in_sizes; (void)n_in; (void)out_size;
    cudaFuncSetAttribute(lstm_mma, cudaFuncAttributeMaxDynamicSharedMemorySize,
                         SM_TOTAL);
    lstm_mma<<<GRID, NTHR, SM_TOTAL>>>(
        (const float*)d_in[0], (const float*)d_in[1], (const float*)d_in[2],
        (const float*)d_in[3], (const float*)d_in[4], (const float*)d_in[5],
        (const float*)d_in[6], (const float*)d_in[7], (const float*)d_in[8],
        (float*)d_out);
}

// round 15
// speedup vs baseline: 1.3798x; 1.3798x over previous
#include <cuda_runtime.h>
#include <cuda_fp16.h>
#include <cstdint>

#define HID   512
#define BATCH 256
#define TLEN  1024
#define GRID  128
#define NTHR  256

// smem byte offsets
#define SM_A      0                      // 96 chunks x 2 mh x 1024B = 196608
#define GSTRIDE   132
#define SM_G0     196608                 // 32 x 132 fp32 = 16896 (single gates buf)
#define SM_WIH1   213504                 // 32 fp32
#define SM_B1     213632
#define SM_B2     213760
#define SM_WLIN   213888                 // 512 fp32
#define SM_TOTAL  215936

// B-fragment image (fp16): [kc(32)][flat_tile(32)][lane(32)][8B]
// 8B = {b0(2 fp16), b1(2 fp16)}; 32 chunks x 8192B = 262144B
__device__ __align__(16) unsigned char g_h1img[2][262144];
__device__ __align__(16) unsigned char g_h2img[2][262144];
__device__ float g_h2f32[2][BATCH * HID];   // [b][u] for the output head
__device__ float g_xT[TLEN * BATCH];        // x transposed [t][b]
__device__ unsigned long long g_epoch;
__device__ unsigned g_cnt;

#define MMA_F16(D, A0, A1, A2, A3, B0, B1)                                    \
    asm volatile(                                                             \
        "mma.sync.aligned.m16n8k16.row.col.f32.f16.f16.f32 "                  \
        "{%0,%1,%2,%3}, {%4,%5,%6,%7}, {%8,%9}, {%0,%1,%2,%3};"               \
        : "+f"((D)[0]), "+f"((D)[1]), "+f"((D)[2]), "+f"((D)[3])              \
        : "r"(A0), "r"(A1), "r"(A2), "r"(A3), "r"(B0), "r"(B1))

__device__ __forceinline__ float sigm_f(float v) {
    return __fdividef(1.f, 1.f + __expf(-v));
}
__device__ __forceinline__ float tanh_f(float v) {
    float e = __expf(2.f * v);
    return 1.f - __fdividef(2.f, e + 1.f);
}

__device__ __forceinline__ void grid_bar(unsigned long long& target, int tid) {
    __threadfence();
    __syncthreads();
    if (tid == 0) {
        target += 1;
        unsigned prev = atomicAdd(&g_cnt, 1u);
        if (prev == GRID - 1) {
            g_cnt = 0;
            __threadfence();
            atomicAdd(&g_epoch, 1ull);
        } else {
            while (*((volatile unsigned long long*)&g_epoch) < target) { }
        }
        __threadfence();
    }
    __syncthreads();
}

// load one quad (4 chunks x 2 tiles) of B fragments; bimg pre-offset by
// nb/ng/lane
__device__ __forceinline__ void loadq(uint2 B[8], const char* bimg, int q) {
#pragma unroll
    for (int j = 0; j < 8; j++)
        B[j] = *(const uint2*)(bimg + (q * 4 + (j >> 1)) * 8192 + (j & 1) * 256);
}

// compute one quad: 4 chunks x (2 mh x 2 tiles x 2 MMAs) = 16 MMAs
__device__ __forceinline__ void compq(float dm[4][4], float dc[4][4],
                                      const char* a0, const char* a1,
                                      int cbase, const uint2 B[8]) {
#pragma unroll
    for (int cl = 0; cl < 4; cl++) {
        int co = (cbase + cl) * 2048;
        uint4 Ah0 = *(const uint4*)(a0 + co);
        uint4 Al0 = *(const uint4*)(a0 + co + 512);
        uint4 Ah1 = *(const uint4*)(a1 + co);
        uint4 Al1 = *(const uint4*)(a1 + co + 512);
#pragma unroll
        for (int t = 0; t < 2; t++) {
            uint2 Bv = B[cl * 2 + t];
            MMA_F16(dm[0 + t], Ah0.x, Ah0.y, Ah0.z, Ah0.w, Bv.x, Bv.y);  // w_hi
            MMA_F16(dc[0 + t], Al0.x, Al0.y, Al0.z, Al0.w, Bv.x, Bv.y);  // w_lo*4096
            MMA_F16(dm[2 + t], Ah1.x, Ah1.y, Ah1.z, Ah1.w, Bv.x, Bv.y);
            MMA_F16(dc[2 + t], Al1.x, Al1.y, Al1.z, Al1.w, Bv.x, Bv.y);
        }
    }
}

// 32-chunk GEMM range with quad-level double buffering
__device__ __forceinline__ void gemm32(float dm[4][4], float dc[4][4],
                                       const char* a0, const char* a1,
                                       const char* bimg) {
    uint2 Ba[8], Bb[8];
    loadq(Ba, bimg, 0);
#pragma unroll
    for (int q = 0; q < 8; q += 2) {
        loadq(Bb, bimg, q + 1);
        compq(dm, dc, a0, a1, q * 4, Ba);
        if (q + 2 < 8) loadq(Ba, bimg, q + 2);
        compq(dm, dc, a0, a1, (q + 1) * 4, Bb);
    }
}

__global__ __launch_bounds__(NTHR, 1)
void lstm_mma(const float* __restrict__ x, const float* __restrict__ W_ih1,
              const float* __restrict__ W_hh1, const float* __restrict__ b1,
              const float* __restrict__ W_ih2, const float* __restrict__ W_hh2,
              const float* __restrict__ b2, const float* __restrict__ W_lin,
              const float* __restrict__ b_lin, float* __restrict__ out)
{
    extern __shared__ char smch[];
    const int tid = threadIdx.x, wid = tid >> 5, lane = tid & 31;
    const int bk = blockIdx.x;
    const int rt = bk >> 1;          // row-tile 0..63 (units rt*8 .. rt*8+7)
    const int nb = bk & 1;           // batch half

    unsigned long long bar_target = 0;
    if (tid == 0) bar_target = *((volatile unsigned long long*)&g_epoch);

    float* gsm  = (float*)(smch + SM_G0);
    float* wih1 = (float*)(smch + SM_WIH1);
    float* b1s  = (float*)(smch + SM_B1);
    float* b2s  = (float*)(smch + SM_B2);
    float* wl   = (float*)(smch + SM_WLIN);

    if (tid < 32) {
        int grow = (tid & 3) * HID + rt * 8 + (tid >> 2);
        wih1[tid] = W_ih1[grow];
        b1s[tid]  = b1[grow];
        b2s[tid]  = b2[grow];
    }
    for (int i = tid; i < HID; i += NTHR) wl[i] = W_lin[i];
    const float blin = b_lin[0];

    // ---- A pack: 96 chunks x 2 mh x 32 lane x 4 regs, fp16 hi + lo*4096 ----
    for (int idx = tid; idx < 96 * 2 * 32 * 4; idx += NTHR) {
        int j = idx & 3, l = (idx >> 2) & 31, mhp = (idx >> 7) & 1, c = idx >> 8;
        int m16row = (j & 1) * 8 + (l >> 2);
        int r = mhp * 16 + m16row;
        int grow = (r & 3) * HID + rt * 8 + (r >> 2);
        int kk0 = ((j >> 1) & 1) * 8 + 2 * (l & 3);
        float w0, w1;
        if (c < 32) {
            int kg = c * 16 + kk0;
            w0 = W_hh1[grow * HID + kg]; w1 = W_hh1[grow * HID + kg + 1];
        } else {
            int kl = (c - 32) * 16 + kk0;
            if (kl < HID) { w0 = W_ih2[grow * HID + kl]; w1 = W_ih2[grow * HID + kl + 1]; }
            else { w0 = W_hh2[grow * HID + kl - HID]; w1 = W_hh2[grow * HID + kl - HID + 1]; }
        }
        __half h0 = __float2half(w0), h1v = __float2half(w1);
        __half l0 = __float2half((w0 - __half2float(h0)) * 4096.f);
        __half l1 = __float2half((w1 - __half2float(h1v)) * 4096.f);
        uint32_t hp = ((uint32_t)__half_as_ushort(h1v) << 16) | __half_as_ushort(h0);
        uint32_t lp = ((uint32_t)__half_as_ushort(l1)  << 16) | __half_as_ushort(l0);
        char* base = smch + SM_A + c * 2048 + mhp * 1024 + l * 16 + j * 4;
        *(uint32_t*)base = hp;
        *(uint32_t*)(base + 512) = lp;
    }

    // ---- global prologue ----
    {
        const int gt = bk * NTHR + tid, gs = GRID * NTHR;
        unsigned long long* z1 = (unsigned long long*)g_h1img[0];
        unsigned long long* z2 = (unsigned long long*)g_h2img[0];
        for (int i = gt; i < 262144 / 8; i += gs) { z1[i] = 0ull; z2[i] = 0ull; }
        for (int i = gt; i < TLEN * BATCH; i += gs)
            g_xT[(i & (TLEN - 1)) * BATCH + (i >> 10)] = x[i];
    }
    grid_bar(bar_target, tid);

    // activation partition: unit u = tid>>5, batches bq..bq+3
    float c1r[4] = {0.f, 0.f, 0.f, 0.f};
    float c2r[4] = {0.f, 0.f, 0.f, 0.f};
    const int u = tid >> 5, bq = (tid & 31) * 4;
    const int ug = rt * 8 + u;
    const int kcw = ug >> 4, kk = ug & 15, kk7 = kk & 7;
    const size_t woffW = (size_t)kcw * 8192 + ((kk < 8) ? 0 : 4) + (kk & 1) * 2;

    // per-warp B base: disjoint n16 slice (flat tiles nb*16 + wid*2, +1)
    const size_t woff = (size_t)nb * 4096 + (size_t)wid * 512 + lane * 8;
    const char* a0 = smch + SM_A + lane * 16;       // mh0
    const char* a1 = a0 + 1024;                     // mh1

    float dm[4][4], dc[4][4];

    for (int t = 0; t < TLEN; t++) {
        const int pr = t & 1, pw = pr ^ 1;

        // ================= phase A: layer-1 gates =================
#pragma unroll
        for (int i = 0; i < 16; i++) { dm[i >> 2][i & 3] = 0.f; dc[i >> 2][i & 3] = 0.f; }
        gemm32(dm, dc, a0, a1, (const char*)g_h1img[pr] + woff);

        {   // merge correction, fragments -> gates smem (cols wid*16..+16)
            int cb = wid * 16 + 2 * (lane & 3);
            int rr = lane >> 2;
#pragma unroll
            for (int mhp = 0; mhp < 2; mhp++)
#pragma unroll
                for (int tl = 0; tl < 2; tl++) {
                    float* dd = dm[mhp * 2 + tl];
                    float* ee = dc[mhp * 2 + tl];
                    *(float2*)&gsm[(mhp * 16 + rr) * GSTRIDE + cb + tl * 8] =
                        make_float2(dd[0] + ee[0] * 2.44140625e-4f,
                                    dd[1] + ee[1] * 2.44140625e-4f);
                    *(float2*)&gsm[(mhp * 16 + rr + 8) * GSTRIDE + cb + tl * 8] =
                        make_float2(dd[2] + ee[2] * 2.44140625e-4f,
                                    dd[3] + ee[3] * 2.44140625e-4f);
                }
        }
        __syncthreads();
        {   // layer-1 activation
            unsigned char* img = g_h1img[pw];
            float4 xv = *(const float4*)&g_xT[t * BATCH + nb * 128 + bq];
            float gv[4][4];
#pragma unroll
            for (int gi_ = 0; gi_ < 4; gi_++) {
                float4 v0 = *(const float4*)&gsm[(4 * u + gi_) * GSTRIDE + bq];
                float bb = b1s[4 * u + gi_];
                float ww = wih1[4 * u + gi_];
                gv[gi_][0] = v0.x + bb + ww * xv.x;
                gv[gi_][1] = v0.y + bb + ww * xv.y;
                gv[gi_][2] = v0.z + bb + ww * xv.z;
                gv[gi_][3] = v0.w + bb + ww * xv.w;
            }
#pragma unroll
            for (int e = 0; e < 4; e++) {
                float i_ = sigm_f(gv[0][e]);
                float f_ = sigm_f(gv[1][e]);
                float o_ = sigm_f(gv[3][e]);
                float c = f_ * c1r[e] + i_ * tanh_f(gv[2][e]);
                c1r[e] = c;
                float hv = o_ * tanh_f(c);
                int bl = bq + e;
                int c32 = bl & 31, tile = c32 >> 3, col8 = c32 & 7;
                int ln = col8 * 4 + (kk7 >> 1);
                size_t off = woffW + (size_t)(nb * 4 + (bl >> 5)) * 1024 + tile * 256 + ln * 8;
                *(__half*)(img + off) = __float2half(hv);
            }
        }

        grid_bar(bar_target, tid);   // the ONLY grid barrier per step

        // ---- output head y(t-1): h2f32[pr] written at B(t-1) ----
        if (t > 0 && wid < 2) {
            int b = 2 * bk + wid;
            const float* hb = g_h2f32[pr] + b * HID;
            float s = 0.f;
#pragma unroll
            for (int i = 0; i < 16; i++) s += wl[lane + 32 * i] * hb[lane + 32 * i];
#pragma unroll
            for (int o = 16; o > 0; o >>= 1) s += __shfl_xor_sync(~0u, s, o);
            if (lane == 0) out[b * TLEN + t - 1] = s + blin;
        }

        // ================= phase B: layer-2 gates =================
#pragma unroll
        for (int i = 0; i < 16; i++) { dm[i >> 2][i & 3] = 0.f; dc[i >> 2][i & 3] = 0.f; }
        gemm32(dm, dc, a0 + 32 * 2048, a1 + 32 * 2048, (const char*)g_h1img[pw] + woff);
        gemm32(dm, dc, a0 + 64 * 2048, a1 + 64 * 2048, (const char*)g_h2img[pr] + woff);

        {
            int cb = wid * 16 + 2 * (lane & 3);
            int rr = lane >> 2;
#pragma unroll
            for (int mhp = 0; mhp < 2; mhp++)
#pragma unroll
                for (int tl = 0; tl < 2; tl++) {
                    float* dd = dm[mhp * 2 + tl];
                    float* ee = dc[mhp * 2 + tl];
                    *(float2*)&gsm[(mhp * 16 + rr) * GSTRIDE + cb + tl * 8] =
                        make_float2(dd[0] + ee[0] * 2.44140625e-4f,
                                    dd[1] + ee[1] * 2.44140625e-4f);
                    *(float2*)&gsm[(mhp * 16 + rr + 8) * GSTRIDE + cb + tl * 8] =
                        make_float2(dd[2] + ee[2] * 2.44140625e-4f,
                                    dd[3] + ee[3] * 2.44140625e-4f);
                }
        }
        __syncthreads();
        {   // layer-2 activation
            unsigned char* img = g_h2img[pw];
            float* h2o = g_h2f32[pw];
            float gv[4][4];
#pragma unroll
            for (int gi_ = 0; gi_ < 4; gi_++) {
                float4 v0 = *(const float4*)&gsm[(4 * u + gi_) * GSTRIDE + bq];
                float bb = b2s[4 * u + gi_];
                gv[gi_][0] = v0.x + bb;
                gv[gi_][1] = v0.y + bb;
                gv[gi_][2] = v0.z + bb;
                gv[gi_][3] = v0.w + bb;
            }
#pragma unroll
            for (int e = 0; e < 4; e++) {
                float i_ = sigm_f(gv[0][e]);
                float f_ = sigm_f(gv[1][e]);
                float o_ = sigm_f(gv[3][e]);
                float c = f_ * c2r[e] + i_ * tanh_f(gv[2][e]);
                c2r[e] = c;
                float hv = o_ * tanh_f(c);
                int bl = bq + e, bg = nb * 128 + bl;
                int c32 = bl & 31, tile = c32 >> 3, col8 = c32 & 7;
                int ln = col8 * 4 + (kk7 >> 1);
                size_t off = woffW + (size_t)(nb * 4 + (bl >> 5)) * 1024 + tile * 256 + ln * 8;
                *(__half*)(img + off) = __float2half(hv);
                h2o[bg * HID + ug] = hv;
            }
        }
        __syncthreads();   // protect gates smem vs next step's stores
    }

    // ---- final output y(T-1) ----
    grid_bar(bar_target, tid);
    if (wid < 2) {
        int b = 2 * bk + wid;
        const float* hb = g_h2f32[0] + b * HID;
        float s = 0.f;
#pragma unroll
        for (int i = 0; i < 16; i++) s += wl[lane + 32 * i] * hb[lane + 32 * i];
#pragma unroll
        for (int o = 16; o > 0; o >>= 1) s += __shfl_xor_sync(~0u, s, o);
        if (lane == 0) out[b * TLEN + TLEN - 1] = s + blin;
    }
}

extern "C" void kernel_launch(void* const* d_in, const int* in_sizes, int n_in,
                              void* d_out, int out_size)
{
    (void)in_sizes; (void)n_in; (void)out_size;
    cudaFuncSetAttribute(lstm_mma, cudaFuncAttributeMaxDynamicSharedMemorySize,
                         SM_TOTAL);
    lstm_mma<<<GRID, NTHR, SM_TOTAL>>>(
        (const float*)d_in[0], (const float*)d_in[1], (const float*)d_in[2],
        (const float*)d_in[3], (const float*)d_in[4], (const float*)d_in[5],
        (const float*)d_in[6], (const float*)d_in[7], (const float*)d_in[8],
        (float*)d_out);
}

// round 16
// speedup vs baseline: 1.7668x; 1.2805x over previous
#include <cuda_runtime.h>
#include <cuda_fp16.h>
#include <cstdint>

#define HID   512
#define BATCH 256
#define TLEN  1024
#define GRID  128
#define NTHR  256

// smem byte offsets
#define SM_A      0                      // 96 chunks x 1024B (hi only) = 98304
#define GSTRIDE   132
#define SM_G0     98304                  // 32 x 132 fp32 = 16896
#define SM_WIH1   115200                 // 32 fp32
#define SM_B1     115328
#define SM_B2     115456
#define SM_WLIN   115584                 // 512 fp32
#define SM_TOTAL  117632

// B-fragment image (fp16): [kc(32)][flat_tile(32)][lane(32)][8B]
// 8B = {b0(2 fp16), b1(2 fp16)}; 32 chunks x 8192B = 262144B
__device__ __align__(16) unsigned char g_h1img[2][262144];
__device__ __align__(16) unsigned char g_h2img[2][262144];
__device__ float g_h2f32[2][BATCH * HID];   // [b][u] for the output head
__device__ float g_xT[TLEN * BATCH];        // x transposed [t][b]
__device__ unsigned long long g_epoch;
__device__ unsigned g_cnt;

#define MMA_F16(D, A0, A1, A2, A3, B0, B1)                                    \
    asm volatile(                                                             \
        "mma.sync.aligned.m16n8k16.row.col.f32.f16.f16.f32 "                  \
        "{%0,%1,%2,%3}, {%4,%5,%6,%7}, {%8,%9}, {%0,%1,%2,%3};"               \
        : "+f"((D)[0]), "+f"((D)[1]), "+f"((D)[2]), "+f"((D)[3])              \
        : "r"(A0), "r"(A1), "r"(A2), "r"(A3), "r"(B0), "r"(B1))

__device__ __forceinline__ float sigm_f(float v) {
    return __fdividef(1.f, 1.f + __expf(-v));
}
__device__ __forceinline__ float tanh_f(float v) {
    float e = __expf(2.f * v);
    return 1.f - __fdividef(2.f, e + 1.f);
}

__device__ __forceinline__ void grid_bar(unsigned long long& target, int tid) {
    __threadfence();
    __syncthreads();
    if (tid == 0) {
        target += 1;
        unsigned prev = atomicAdd(&g_cnt, 1u);
        if (prev == GRID - 1) {
            g_cnt = 0;
            __threadfence();
            atomicAdd(&g_epoch, 1ull);
        } else {
            while (*((volatile unsigned long long*)&g_epoch) < target) { }
        }
        __threadfence();
    }
    __syncthreads();
}

// load one quad (4 chunks x 2 tiles) of B fragments; bimg pre-offset
__device__ __forceinline__ void loadq(uint2 B[8], const char* bimg, int q) {
#pragma unroll
    for (int j = 0; j < 8; j++)
        B[j] = *(const uint2*)(bimg + (q * 4 + (j >> 1)) * 8192 + (j & 1) * 256);
}

// compute one quad: 4 chunks x (2 mh x 2 tiles x 1 MMA) = 8 MMAs
__device__ __forceinline__ void compq(float dm[4][4],
                                      const char* a0, int cbase, const uint2 B[8]) {
#pragma unroll
    for (int cl = 0; cl < 4; cl++) {
        int co = (cbase + cl) * 1024;
        uint4 Ah0 = *(const uint4*)(a0 + co);
        uint4 Ah1 = *(const uint4*)(a0 + co + 512);
#pragma unroll
        for (int t = 0; t < 2; t++) {
            uint2 Bv = B[cl * 2 + t];
            MMA_F16(dm[0 + t], Ah0.x, Ah0.y, Ah0.z, Ah0.w, Bv.x, Bv.y);
            MMA_F16(dm[2 + t], Ah1.x, Ah1.y, Ah1.z, Ah1.w, Bv.x, Bv.y);
        }
    }
}

// 32-chunk GEMM range with quad-level double buffering
__device__ __forceinline__ void gemm32(float dm[4][4], const char* a0,
                                       const char* bimg) {
    uint2 Ba[8], Bb[8];
    loadq(Ba, bimg, 0);
#pragma unroll
    for (int q = 0; q < 8; q += 2) {
        loadq(Bb, bimg, q + 1);
        compq(dm, a0, q * 4, Ba);
        if (q + 2 < 8) loadq(Ba, bimg, q + 2);
        compq(dm, a0, (q + 1) * 4, Bb);
    }
}

__global__ __launch_bounds__(NTHR, 1)
void lstm_mma(const float* __restrict__ x, const float* __restrict__ W_ih1,
              const float* __restrict__ W_hh1, const float* __restrict__ b1,
              const float* __restrict__ W_ih2, const float* __restrict__ W_hh2,
              const float* __restrict__ b2, const float* __restrict__ W_lin,
              const float* __restrict__ b_lin, float* __restrict__ out)
{
    extern __shared__ char smch[];
    const int tid = threadIdx.x, wid = tid >> 5, lane = tid & 31;
    const int bk = blockIdx.x;
    const int rt = bk >> 1;          // row-tile 0..63 (units rt*8 .. rt*8+7)
    const int nb = bk & 1;           // batch half

    unsigned long long bar_target = 0;
    if (tid == 0) bar_target = *((volatile unsigned long long*)&g_epoch);

    float* gsm  = (float*)(smch + SM_G0);
    float* wih1 = (float*)(smch + SM_WIH1);
    float* b1s  = (float*)(smch + SM_B1);
    float* b2s  = (float*)(smch + SM_B2);
    float* wl   = (float*)(smch + SM_WLIN);

    if (tid < 32) {
        int grow = (tid & 3) * HID + rt * 8 + (tid >> 2);
        wih1[tid] = W_ih1[grow];
        b1s[tid]  = b1[grow];
        b2s[tid]  = b2[grow];
    }
    for (int i = tid; i < HID; i += NTHR) wl[i] = W_lin[i];
    const float blin = b_lin[0];

    // ---- A pack: 96 chunks x 2 mh x 32 lane x 4 regs, fp16 (hi only) ----
    for (int idx = tid; idx < 96 * 2 * 32 * 4; idx += NTHR) {
        int j = idx & 3, l = (idx >> 2) & 31, mhp = (idx >> 7) & 1, c = idx >> 8;
        int m16row = (j & 1) * 8 + (l >> 2);
        int r = mhp * 16 + m16row;
        int grow = (r & 3) * HID + rt * 8 + (r >> 2);
        int kk0 = ((j >> 1) & 1) * 8 + 2 * (l & 3);
        float w0, w1;
        if (c < 32) {
            int kg = c * 16 + kk0;
            w0 = W_hh1[grow * HID + kg]; w1 = W_hh1[grow * HID + kg + 1];
        } else {
            int kl = (c - 32) * 16 + kk0;
            if (kl < HID) { w0 = W_ih2[grow * HID + kl]; w1 = W_ih2[grow * HID + kl + 1]; }
            else { w0 = W_hh2[grow * HID + kl - HID]; w1 = W_hh2[grow * HID + kl - HID + 1]; }
        }
        __half h0 = __float2half(w0), h1v = __float2half(w1);
        uint32_t hp = ((uint32_t)__half_as_ushort(h1v) << 16) | __half_as_ushort(h0);
        *(uint32_t*)(smch + SM_A + c * 1024 + mhp * 512 + l * 16 + j * 4) = hp;
    }

    // ---- global prologue ----
    {
        const int gt = bk * NTHR + tid, gs = GRID * NTHR;
        unsigned long long* z1 = (unsigned long long*)g_h1img[0];
        unsigned long long* z2 = (unsigned long long*)g_h2img[0];
        for (int i = gt; i < 262144 / 8; i += gs) { z1[i] = 0ull; z2[i] = 0ull; }
        for (int i = gt; i < TLEN * BATCH; i += gs)
            g_xT[(i & (TLEN - 1)) * BATCH + (i >> 10)] = x[i];
    }
    grid_bar(bar_target, tid);

    // activation partition: unit u = tid>>5, batches bq..bq+3
    float c1r[4] = {0.f, 0.f, 0.f, 0.f};
    float c2r[4] = {0.f, 0.f, 0.f, 0.f};
    const int u = tid >> 5, bq = (tid & 31) * 4;
    const int ug = rt * 8 + u;
    const int kcw = ug >> 4, kk = ug & 15, kk7 = kk & 7;
    const size_t woffW = (size_t)kcw * 8192 + ((kk < 8) ? 0 : 4) + (kk & 1) * 2;

    // per-warp B base: disjoint n16 slice (flat tiles nb*16 + wid*2, +1)
    const size_t woff = (size_t)nb * 4096 + (size_t)wid * 512 + lane * 8;
    const char* a0 = smch + SM_A + lane * 16;

    float dm[4][4];

    for (int t = 0; t < TLEN; t++) {
        const int pr = t & 1, pw = pr ^ 1;

        // ================= phase A: layer-1 gates =================
#pragma unroll
        for (int i = 0; i < 16; i++) dm[i >> 2][i & 3] = 0.f;
        gemm32(dm, a0, (const char*)g_h1img[pr] + woff);

        {   // fragments -> gates smem (cols wid*16..+16)
            int cb = wid * 16 + 2 * (lane & 3);
            int rr = lane >> 2;
#pragma unroll
            for (int mhp = 0; mhp < 2; mhp++)
#pragma unroll
                for (int tl = 0; tl < 2; tl++) {
                    float* dd = dm[mhp * 2 + tl];
                    *(float2*)&gsm[(mhp * 16 + rr) * GSTRIDE + cb + tl * 8] =
                        make_float2(dd[0], dd[1]);
                    *(float2*)&gsm[(mhp * 16 + rr + 8) * GSTRIDE + cb + tl * 8] =
                        make_float2(dd[2], dd[3]);
                }
        }
        __syncthreads();
        {   // layer-1 activation
            unsigned char* img = g_h1img[pw];
            float4 xv = *(const float4*)&g_xT[t * BATCH + nb * 128 + bq];
            float gv[4][4];
#pragma unroll
            for (int gi_ = 0; gi_ < 4; gi_++) {
                float4 v0 = *(const float4*)&gsm[(4 * u + gi_) * GSTRIDE + bq];
                float bb = b1s[4 * u + gi_];
                float ww = wih1[4 * u + gi_];
                gv[gi_][0] = v0.x + bb + ww * xv.x;
                gv[gi_][1] = v0.y + bb + ww * xv.y;
                gv[gi_][2] = v0.z + bb + ww * xv.z;
                gv[gi_][3] = v0.w + bb + ww * xv.w;
            }
#pragma unroll
            for (int e = 0; e < 4; e++) {
                float i_ = sigm_f(gv[0][e]);
                float f_ = sigm_f(gv[1][e]);
                float o_ = sigm_f(gv[3][e]);
                float c = f_ * c1r[e] + i_ * tanh_f(gv[2][e]);
                c1r[e] = c;
                float hv = o_ * tanh_f(c);
                int bl = bq + e;
                int c32 = bl & 31, tile = c32 >> 3, col8 = c32 & 7;
                int ln = col8 * 4 + (kk7 >> 1);
                size_t off = woffW + (size_t)(nb * 4 + (bl >> 5)) * 1024 + tile * 256 + ln * 8;
                *(__half*)(img + off) = __float2half(hv);
            }
        }

        grid_bar(bar_target, tid);   // the ONLY grid barrier per step

        // ---- output head y(t-1): h2f32[pr] written at B(t-1) ----
        if (t > 0 && wid < 2) {
            int b = 2 * bk + wid;
            const float* hb = g_h2f32[pr] + b * HID;
            float s = 0.f;
#pragma unroll
            for (int i = 0; i < 16; i++) s += wl[lane + 32 * i] * hb[lane + 32 * i];
#pragma unroll
            for (int o = 16; o > 0; o >>= 1) s += __shfl_xor_sync(~0u, s, o);
            if (lane == 0) out[b * TLEN + t - 1] = s + blin;
        }

        // ================= phase B: layer-2 gates =================
#pragma unroll
        for (int i = 0; i < 16; i++) dm[i >> 2][i & 3] = 0.f;
        gemm32(dm, a0 + 32 * 1024, (const char*)g_h1img[pw] + woff);
        gemm32(dm, a0 + 64 * 1024, (const char*)g_h2img[pr] + woff);

        {
            int cb = wid * 16 + 2 * (lane & 3);
            int rr = lane >> 2;
#pragma unroll
            for (int mhp = 0; mhp < 2; mhp++)
#pragma unroll
                for (int tl = 0; tl < 2; tl++) {
                    float* dd = dm[mhp * 2 + tl];
                    *(float2*)&gsm[(mhp * 16 + rr) * GSTRIDE + cb + tl * 8] =
                        make_float2(dd[0], dd[1]);
                    *(float2*)&gsm[(mhp * 16 + rr + 8) * GSTRIDE + cb + tl * 8] =
                        make_float2(dd[2], dd[3]);
                }
        }
        __syncthreads();
        {   // layer-2 activation
            unsigned char* img = g_h2img[pw];
            float* h2o = g_h2f32[pw];
            float gv[4][4];
#pragma unroll
            for (int gi_ = 0; gi_ < 4; gi_++) {
                float4 v0 = *(const float4*)&gsm[(4 * u + gi_) * GSTRIDE + bq];
                float bb = b2s[4 * u + gi_];
                gv[gi_][0] = v0.x + bb;
                gv[gi_][1] = v0.y + bb;
                gv[gi_][2] = v0.z + bb;
                gv[gi_][3] = v0.w + bb;
            }
#pragma unroll
            for (int e = 0; e < 4; e++) {
                float i_ = sigm_f(gv[0][e]);
                float f_ = sigm_f(gv[1][e]);
                float o_ = sigm_f(gv[3][e]);
                float c = f_ * c2r[e] + i_ * tanh_f(gv[2][e]);
                c2r[e] = c;
                float hv = o_ * tanh_f(c);
                int bl = bq + e, bg = nb * 128 + bl;
                int c32 = bl & 31, tile = c32 >> 3, col8 = c32 & 7;
                int ln = col8 * 4 + (kk7 >> 1);
                size_t off = woffW + (size_t)(nb * 4 + (bl >> 5)) * 1024 + tile * 256 + ln * 8;
                *(__half*)(img + off) = __float2half(hv);
                h2o[bg * HID + ug] = hv;
            }
        }
        __syncthreads();   // protect gates smem vs next step's stores
    }

    // ---- final output y(T-1) ----
    grid_bar(bar_target, tid);
    if (wid < 2) {
        int b = 2 * bk + wid;
        const float* hb = g_h2f32[0] + b * HID;
        float s = 0.f;
#pragma unroll
        for (int i = 0; i < 16; i++) s += wl[lane + 32 * i] * hb[lane + 32 * i];
#pragma unroll
        for (int o = 16; o > 0; o >>= 1) s += __shfl_xor_sync(~0u, s, o);
        if (lane == 0) out[b * TLEN + TLEN - 1] = s + blin;
    }
}

extern "C" void kernel_launch(void* const* d_in, const int* in_sizes, int n_in,
                              void* d_out, int out_size)
{
    (void)in_sizes; (void)n_in; (void)out_size;
    cudaFuncSetAttribute(lstm_mma, cudaFuncAttributeMaxDynamicSharedMemorySize,
                         SM_TOTAL);
    lstm_mma<<<GRID, NTHR, SM_TOTAL>>>(
        (const float*)d_in[0], (const float*)d_in[1], (const float*)d_in[2],
        (const float*)d_in[3], (const float*)d_in[4], (const float*)d_in[5],
        (const float*)d_in[6], (const float*)d_in[7], (const float*)d_in[8],
        (float*)d_out);
}